// round 11
// baseline (speedup 1.0000x reference)
#include <cuda_runtime.h>
#include <math.h>

// Problem constants
#define BATCH 64
#define SEQ   512
#define HID   1024
#define EMB   256
#define NCHAR 128

// Geometry: 128 persistent CTAs = 4 batch-groups (tb) x 32 j-tiles (tj).
// 256 threads = 8 warps = 2/SMSP; warp = k-block of 128; lane covers 16b x 4j.
#define GRID     128
#define NTHREADS 256
#define BT       16      // batch rows per CTA
#define JT       32      // hidden rows per CTA

#define SW_STRIDE 36     // W row stride (words): balanced 4-wf LDS.128
#define SH_STRIDE 20     // h row stride (words): conflict-free 4-ks LDSV2
#define SP_STRIDE 18     // partial row stride (words): 16 + 2 pad

#define SW_FLOATS (HID * SW_STRIDE)            // 36864
#define SH_FLOATS (HID * SH_STRIDE)            // 20480
#define SMEM_BYTES ((SW_FLOATS + SH_FLOATS) * 4)   // 229,376 B

typedef unsigned long long u64;

// packed f32x2 (sm_100+): one SASS FFMA2 = 2 FMAs
#define FMA2(d, a, b)    asm("fma.rn.f32x2 %0, %1, %2, %0;" : "+l"(d) : "l"(a), "l"(b))
#define ADD2(d, a)       asm("add.rn.f32x2 %0, %0, %1;" : "+l"(d) : "l"(a))
#define PACK2(d, lo, hi) asm("mov.b64 %0, {%1, %2};" : "=l"(d) : "f"(lo), "f"(hi))
#define UNPACK2(lo, hi, v) asm("mov.b64 {%0, %1}, %2;" : "=f"(lo), "=f"(hi) : "l"(v))
#define LDSV2(a, b, addr) \
    asm volatile("ld.shared.v2.b64 {%0,%1}, [%2];" : "=l"(a), "=l"(b) : "r"(addr))
#define STS64(addr, v)   asm volatile("st.shared.b64 [%0], %1;" :: "r"(addr), "l"(v))

// Device-global scratch
__device__ float g_U[NCHAR * HID];           // U = embeddings @ W_ih^T
__device__ float g_h[2][BATCH * HID];        // ping-pong hidden state, batch-major
__device__ unsigned g_count[4 * 32];         // 4 group barrier counters (128B apart)
__device__ volatile unsigned g_sense[4 * 32];// sense; ends at 0 (514 phases/launch)

// ---------------------------------------------------------------------------
// 32-CTA group barrier (threadfence version — proven in best runs).
// ---------------------------------------------------------------------------
__device__ __forceinline__ void gbar(unsigned* cnt, volatile unsigned* sns, unsigned s) {
    __syncthreads();
    if (threadIdx.x == 0) {
        __threadfence();
        if (atomicAdd(cnt, 1u) == 31u) {
            *cnt = 0;
            __threadfence();
            *sns = s;
        } else {
            while (*sns != s) { }
            __threadfence();
        }
    }
    __syncthreads();
}

// ---------------------------------------------------------------------------
// Kernel 0: U[c][j] = sum_e emb[c][e] * W_ih[j][e]
// ---------------------------------------------------------------------------
__global__ void u_kernel(const float* __restrict__ emb, const float* __restrict__ wih) {
    int gt   = blockIdx.x * blockDim.x + threadIdx.x;
    int warp = gt >> 5;
    int lane = gt & 31;
    int e0   = lane * 8;
    for (int i = 0; i < 32; i++) {
        int o = warp * 32 + i;
        int c = o >> 10;
        int j = o & 1023;
        const float4* ep = (const float4*)(emb + c * EMB + e0);
        const float4* wp = (const float4*)(wih + j * EMB + e0);
        float4 e1 = __ldg(ep),     e2 = __ldg(ep + 1);
        float4 w1 = __ldg(wp),     w2 = __ldg(wp + 1);
        float acc = e1.x*w1.x + e1.y*w1.y + e1.z*w1.z + e1.w*w1.w
                  + e2.x*w2.x + e2.y*w2.y + e2.z*w2.z + e2.w*w2.w;
        acc += __shfl_xor_sync(0xffffffffu, acc, 16);
        acc += __shfl_xor_sync(0xffffffffu, acc, 8);
        acc += __shfl_xor_sync(0xffffffffu, acc, 4);
        acc += __shfl_xor_sync(0xffffffffu, acc, 2);
        acc += __shfl_xor_sync(0xffffffffu, acc, 1);
        if (lane == 0) g_U[c * HID + j] = acc;
    }
}

// ---------------------------------------------------------------------------
// Persistent RNN scan.
// Warp w = k-block of 128 (W read EXACTLY once per step per CTA).
// Lane l: jg = l&7 (4 j's), ks = l>>3 (k interleave); k = w*128 + i*4 + ks.
// Per iter: 4x ld.shared.v2.b64 h (16 batches as 8 native f32x2 pairs,
// conflict-free broadcast, 1 wf each) + 1 LDS.128 W (balanced 4 wf)
// + 4 dup MOV + 32 FFMA2.  SMEM: ~2048 wf/SM/step < 4096-cyc FFMA2 floor.
// ---------------------------------------------------------------------------
__global__ void __launch_bounds__(NTHREADS, 1) rnn_kernel(
    const int*   __restrict__ tids,
    const float* __restrict__ whh,
    const float* __restrict__ h0,
    const float* __restrict__ wproj,
    const float* __restrict__ bproj,
    float*       __restrict__ out)
{
    extern __shared__ float smem[];
    float* sW = smem;                // [1024][36]  W slice transposed (32 j + pad)
    float* sH = smem + SW_FLOATS;    // [1024][20]  h tile [k][16 b + pad]
    float* sP = sH;                  // [8*32][18]  partials — ALIASES sH (sync-guarded)

    const int tid = threadIdx.x;
    const int cta = blockIdx.x;
    const int tb  = cta >> 5;        // 0..3
    const int tj  = cta & 31;        // 0..31
    const int b0  = tb * BT;
    const int j0  = tj * JT;
    unsigned*          cnt = &g_count[tb * 32];
    volatile unsigned* sns = &g_sense[tb * 32];

    // one-time: W_hh slice transposed into SMEM (coalesced LDG rows)
    for (int idx = tid; idx < JT * HID; idx += NTHREADS) {
        int jj = idx >> 10;
        int k  = idx & 1023;
        sW[k * SW_STRIDE + jj] = whh[(j0 + jj) * HID + k];
    }
    // one-time: init h ping buffer (this CTA's 16b x 32j tile)
    for (int idx = tid; idx < BT * JT; idx += NTHREADS) {
        int bb = idx >> 5;
        int jj = idx & 31;
        g_h[0][(b0 + bb) * HID + (j0 + jj)] = h0[j0 + jj];
    }

    unsigned bs = 1;
    gbar(cnt, sns, bs);                          // phase 1 (init visible)

    const int w  = tid >> 5;         // k-block 0..7
    const int l  = tid & 31;
    const int jg = l & 7;            // 4 j's: jg*4..+3
    const int ks = l >> 3;           // 0..3

    const unsigned shb = (unsigned)__cvta_generic_to_shared(sH);
    const unsigned ha0 = shb + (unsigned)((w * 128 + ks) * SH_STRIDE) * 4u;
    const float* wp0 = sW + (w * 128 + ks) * SW_STRIDE + jg * 4;

    // staging: thread (p = batch pair, kc = 32-k chunk)
    const int st_p  = tid & 7;
    const int st_kc = tid >> 3;      // 0..31

    // combine: thread -> (cj, cbp): outputs (b0+2cbp, j0+cj) and (b0+2cbp+1, j0+cj)
    const int cj  = tid & 31;
    const int cbp = tid >> 5;        // 0..7

    for (int s = 0; s < SEQ; s++) {
        const int cur = s & 1;
        const int nxt = cur ^ 1;

        // prefetch epilogue operands (hidden under staging + compute)
        const int   c0 = __ldg(&tids[(b0 + 2 * cbp) * SEQ + s]);
        const int   c1 = __ldg(&tids[(b0 + 2 * cbp + 1) * SEQ + s]);
        const float u0 = __ldg(&g_U[c0 * HID + j0 + cj]);
        const float u1 = __ldg(&g_U[c1 * HID + j0 + cj]);

        // ---- stage h tile: sH[k][bb] as f32x2 batch pairs ----
        {
            const float* r0 = g_h[cur] + (b0 + 2 * st_p) * HID + st_kc * 32;
            const float* r1 = r0 + HID;
            unsigned sa = shb + (unsigned)((st_kc * 32) * SH_STRIDE + 2 * st_p) * 4u;
            #pragma unroll
            for (int it = 0; it < 8; it++) {
                float4 A = __ldcg((const float4*)(r0 + it * 4));
                float4 B = __ldcg((const float4*)(r1 + it * 4));
                unsigned a = sa + (unsigned)(it * 4 * SH_STRIDE) * 4u;
                u64 v;
                PACK2(v, A.x, B.x); STS64(a, v);
                PACK2(v, A.y, B.y); STS64(a + SH_STRIDE * 4, v);
                PACK2(v, A.z, B.z); STS64(a + 2 * SH_STRIDE * 4, v);
                PACK2(v, A.w, B.w); STS64(a + 3 * SH_STRIDE * 4, v);
            }
        }
        __syncthreads();

        // ---- packed f32x2 GEMM: 16b x 4j per lane over 32 k's ----
        u64 acc[8][4];   // [batch pair][j]
        #pragma unroll
        for (int bp = 0; bp < 8; bp++)
            #pragma unroll
            for (int jc = 0; jc < 4; jc++) acc[bp][jc] = 0ull;

        unsigned ha = ha0;
        const float* wp = wp0;
        #pragma unroll 4
        for (int kk = 0; kk < 32; kk++) {
            u64 h0r, h1r, h2r, h3r, h4r, h5r, h6r, h7r;
            LDSV2(h0r, h1r, ha);
            LDSV2(h2r, h3r, ha + 16);
            LDSV2(h4r, h5r, ha + 32);
            LDSV2(h6r, h7r, ha + 48);
            float4 wv = *(const float4*)wp;
            ha += 4 * SH_STRIDE * 4;
            wp += 4 * SW_STRIDE;

            u64 wd0, wd1, wd2, wd3;
            PACK2(wd0, wv.x, wv.x); PACK2(wd1, wv.y, wv.y);
            PACK2(wd2, wv.z, wv.z); PACK2(wd3, wv.w, wv.w);

            FMA2(acc[0][0], h0r, wd0); FMA2(acc[0][1], h0r, wd1);
            FMA2(acc[0][2], h0r, wd2); FMA2(acc[0][3], h0r, wd3);
            FMA2(acc[1][0], h1r, wd0); FMA2(acc[1][1], h1r, wd1);
            FMA2(acc[1][2], h1r, wd2); FMA2(acc[1][3], h1r, wd3);
            FMA2(acc[2][0], h2r, wd0); FMA2(acc[2][1], h2r, wd1);
            FMA2(acc[2][2], h2r, wd2); FMA2(acc[2][3], h2r, wd3);
            FMA2(acc[3][0], h3r, wd0); FMA2(acc[3][1], h3r, wd1);
            FMA2(acc[3][2], h3r, wd2); FMA2(acc[3][3], h3r, wd3);
            FMA2(acc[4][0], h4r, wd0); FMA2(acc[4][1], h4r, wd1);
            FMA2(acc[4][2], h4r, wd2); FMA2(acc[4][3], h4r, wd3);
            FMA2(acc[5][0], h5r, wd0); FMA2(acc[5][1], h5r, wd1);
            FMA2(acc[5][2], h5r, wd2); FMA2(acc[5][3], h5r, wd3);
            FMA2(acc[6][0], h6r, wd0); FMA2(acc[6][1], h6r, wd1);
            FMA2(acc[6][2], h6r, wd2); FMA2(acc[6][3], h6r, wd3);
            FMA2(acc[7][0], h7r, wd0); FMA2(acc[7][1], h7r, wd1);
            FMA2(acc[7][2], h7r, wd2); FMA2(acc[7][3], h7r, wd3);
        }

        // ---- reduce over ks (lane bits 3,4), packed adds ----
        #pragma unroll
        for (int bp = 0; bp < 8; bp++)
            #pragma unroll
            for (int jc = 0; jc < 4; jc++) {
                u64 t;
                t = __shfl_xor_sync(0xffffffffu, acc[bp][jc], 8);  ADD2(acc[bp][jc], t);
                t = __shfl_xor_sync(0xffffffffu, acc[bp][jc], 16); ADD2(acc[bp][jc], t);
            }

        __syncthreads();   // all sH reads done before stash overwrites (sP aliases sH)

        // ---- stash: row per (kblock w, local j), 8 bpair u64 per row ----
        if (ks == 0) {
            #pragma unroll
            for (int jc = 0; jc < 4; jc++) {
                float* row = sP + (w * JT + jg * 4 + jc) * SP_STRIDE;
                #pragma unroll
                for (int bp = 0; bp < 8; bp++)
                    *(u64*)(row + bp * 2) = acc[bp][jc];
            }
        }
        __syncthreads();

        // ---- combine 8 k-blocks (packed), add U, tanh, store next h ----
        {
            u64 sacc = 0ull;
            #pragma unroll
            for (int kb = 0; kb < 8; kb++) {
                u64 v = *(const u64*)(sP + (kb * JT + cj) * SP_STRIDE + cbp * 2);
                ADD2(sacc, v);
            }
            float lo, hi;
            UNPACK2(lo, hi, sacc);
            float hn0 = tanhf(lo + u0);
            float hn1 = tanhf(hi + u1);
            __stcg(&g_h[nxt][(b0 + 2 * cbp) * HID + j0 + cj], hn0);
            __stcg(&g_h[nxt][(b0 + 2 * cbp + 1) * HID + j0 + cj], hn1);
        }

        bs ^= 1; gbar(cnt, sns, bs);                 // phases 2..513
    }

    // ---- final projection: out[b][c] = h_final[b] . W_proj[c] + b_proj[c] ----
    // After s=511, final h is in g_h[0].
    if (tid < 64) {
        const int bb = tid >> 2;
        const int cc = tid & 3;
        const int b  = b0 + bb;
        const int ch = tj * 4 + cc;
        const float* hp = g_h[0] + b * HID;
        const float* wp = wproj + ch * HID;
        float acc2 = 0.0f;
        #pragma unroll 4
        for (int k = 0; k < HID; k += 4) {
            float4 hv = __ldcg((const float4*)(hp + k));
            float4 wv = *(const float4*)(wp + k);
            acc2 += hv.x*wv.x + hv.y*wv.y + hv.z*wv.z + hv.w*wv.w;
        }
        out[b * NCHAR + ch] = acc2 + bproj[ch];
    }

    bs ^= 1; gbar(cnt, sns, bs);                     // phase 514 -> sense back to 0
}

// ---------------------------------------------------------------------------
// Launch: graph-capturable, no allocations, no syncs.
// Inputs: t, embeddings, W_ih, W_hh, h0, W_proj, b_proj.
// ---------------------------------------------------------------------------
extern "C" void kernel_launch(void* const* d_in, const int* in_sizes, int n_in,
                              void* d_out, int out_size)
{
    const int*   t     = (const int*)  d_in[0];
    const float* emb   = (const float*)d_in[1];
    const float* wih   = (const float*)d_in[2];
    const float* whh   = (const float*)d_in[3];
    const float* h0    = (const float*)d_in[4];
    const float* wproj = (const float*)d_in[5];
    const float* bproj = (const float*)d_in[6];
    float*       out   = (float*)d_out;

    cudaFuncSetAttribute(rnn_kernel, cudaFuncAttributeMaxDynamicSharedMemorySize, SMEM_BYTES);

    u_kernel<<<512, 256>>>(emb, wih);
    rnn_kernel<<<GRID, NTHREADS, SMEM_BYTES>>>(t, whh, h0, wproj, bproj, out);
}